// round 4
// baseline (speedup 1.0000x reference)
#include <cuda_runtime.h>
#include <cuda_bf16.h>

#define N_TOK 4096
#define DMODEL 1024
#define NHEAD  16
#define HD     64

// Scratch (allocation-free rule: __device__ globals)
__device__ float g_Q[N_TOK * DMODEL];
__device__ float g_K[N_TOK * DMODEL];
__device__ float g_V[N_TOK * DMODEL];
__device__ float g_C[N_TOK * DMODEL];

// ---------------------------------------------------------------------------
// C[M,N] = A[M,K] @ B[K,N] (+ bias), 64x64 tile, BK=16, 256 threads, 4x4/thread
// ---------------------------------------------------------------------------
template <bool HAS_BIAS>
__global__ void __launch_bounds__(256) sgemm64(const float* __restrict__ A,
                                               const float* __restrict__ B,
                                               const float* __restrict__ bias,
                                               float* __restrict__ C,
                                               int M, int N, int K)
{
    __shared__ float As[64][16];
    __shared__ float Bs[16][64];

    const int t  = threadIdx.x;
    const int tx = t & 15;        // 0..15  -> N micro
    const int ty = t >> 4;        // 0..15  -> M micro
    const int bm = blockIdx.y * 64;
    const int bn = blockIdx.x * 64;

    // load mapping
    const int rowA = t >> 2;            // 0..63
    const int ka   = (t & 3) * 4;       // 0,4,8,12
    const int rowB = t >> 4;            // 0..15
    const int cb   = (t & 15) * 4;      // 0..60

    const float* Aptr = A + (size_t)(bm + rowA) * K + ka;
    const float* Bptr = B + (size_t)rowB * N + bn + cb;

    float acc[4][4];
#pragma unroll
    for (int i = 0; i < 4; i++)
#pragma unroll
        for (int j = 0; j < 4; j++) acc[i][j] = 0.0f;

    for (int k0 = 0; k0 < K; k0 += 16) {
        float4 av = *(const float4*)(Aptr + k0);
        float4 bv = *(const float4*)(Bptr + (size_t)k0 * N);
        *(float4*)&As[rowA][ka] = av;
        *(float4*)&Bs[rowB][cb] = bv;
        __syncthreads();

#pragma unroll
        for (int kk = 0; kk < 16; kk++) {
            float a0 = As[ty * 4 + 0][kk];
            float a1 = As[ty * 4 + 1][kk];
            float a2 = As[ty * 4 + 2][kk];
            float a3 = As[ty * 4 + 3][kk];
            float4 b = *(const float4*)&Bs[kk][tx * 4];
            acc[0][0] += a0 * b.x; acc[0][1] += a0 * b.y; acc[0][2] += a0 * b.z; acc[0][3] += a0 * b.w;
            acc[1][0] += a1 * b.x; acc[1][1] += a1 * b.y; acc[1][2] += a1 * b.z; acc[1][3] += a1 * b.w;
            acc[2][0] += a2 * b.x; acc[2][1] += a2 * b.y; acc[2][2] += a2 * b.z; acc[2][3] += a2 * b.w;
            acc[3][0] += a3 * b.x; acc[3][1] += a3 * b.y; acc[3][2] += a3 * b.z; acc[3][3] += a3 * b.w;
        }
        __syncthreads();
    }

    float4 bias_v = make_float4(0.f, 0.f, 0.f, 0.f);
    if (HAS_BIAS) bias_v = *(const float4*)(bias + bn + tx * 4);

#pragma unroll
    for (int i = 0; i < 4; i++) {
        const int row = bm + ty * 4 + i;
        float4 out;
        out.x = acc[i][0] + bias_v.x;
        out.y = acc[i][1] + bias_v.y;
        out.z = acc[i][2] + bias_v.z;
        out.w = acc[i][3] + bias_v.w;
        *(float4*)(C + (size_t)row * N + bn + tx * 4) = out;
    }
}

// ---------------------------------------------------------------------------
// Causal flash attention, fp32. One CTA = (64 query rows, 1 head), 64 threads.
// Thread owns one query row: q[64], o[64] in registers; K/V 64x64 tiles in SMEM.
// ---------------------------------------------------------------------------
__global__ void __launch_bounds__(64) flash_attn(const float* __restrict__ Q,
                                                 const float* __restrict__ K,
                                                 const float* __restrict__ V,
                                                 float* __restrict__ O)
{
    __shared__ float Ks[64][64];
    __shared__ float Vs[64][64];

    const int t  = threadIdx.x;
    const int qb = blockIdx.x;      // query block 0..63
    const int h  = blockIdx.y;      // head 0..15
    const int gi = qb * 64 + t;     // global query row
    const float LOG2E = 1.4426950408889634f;
    const float scale = 0.125f;     // 1/sqrt(64)

    // load q row, pre-scaled
    float q[64];
    {
        const float* qptr = Q + (size_t)gi * DMODEL + h * HD;
#pragma unroll
        for (int d4 = 0; d4 < 16; d4++) {
            float4 v = *(const float4*)(qptr + d4 * 4);
            q[d4 * 4 + 0] = v.x * scale;
            q[d4 * 4 + 1] = v.y * scale;
            q[d4 * 4 + 2] = v.z * scale;
            q[d4 * 4 + 3] = v.w * scale;
        }
    }

    float o[64];
#pragma unroll
    for (int d = 0; d < 64; d++) o[d] = 0.0f;
    float m_run = -1e30f;
    float l_run = 0.0f;

    const int nkb = qb + 1;         // causal: only key blocks <= qb
    for (int kb = 0; kb < nkb; kb++) {
        const int j0 = kb * 64;
        // cooperative load of K/V tiles (64x64 each), float4, coalesced
        const float* kbase = K + (size_t)j0 * DMODEL + h * HD;
        const float* vbase = V + (size_t)j0 * DMODEL + h * HD;
#pragma unroll
        for (int r = 0; r < 16; r++) {
            int f   = r * 64 + t;        // float4 index 0..1023
            int row = f >> 4;
            int c4  = (f & 15) * 4;
            *(float4*)&Ks[row][c4] = *(const float4*)(kbase + (size_t)row * DMODEL + c4);
            *(float4*)&Vs[row][c4] = *(const float4*)(vbase + (size_t)row * DMODEL + c4);
        }
        __syncthreads();

        const bool diag = (kb == qb);

#pragma unroll 1
        for (int c = 0; c < 4; c++) {      // 16-key chunks
            float s[16];
#pragma unroll
            for (int jj = 0; jj < 16; jj++) {
                const int j = c * 16 + jj;
                float acc0 = 0.f, acc1 = 0.f;
#pragma unroll
                for (int d4 = 0; d4 < 16; d4++) {
                    float4 kv = *(const float4*)&Ks[j][d4 * 4];
                    acc0 += q[d4 * 4 + 0] * kv.x;
                    acc1 += q[d4 * 4 + 1] * kv.y;
                    acc0 += q[d4 * 4 + 2] * kv.z;
                    acc1 += q[d4 * 4 + 3] * kv.w;
                }
                s[jj] = acc0 + acc1;
            }
            if (diag) {
#pragma unroll
                for (int jj = 0; jj < 16; jj++)
                    if (j0 + c * 16 + jj > gi) s[jj] = -1e30f;
            }
            // online softmax update
            float m_new = m_run;
#pragma unroll
            for (int jj = 0; jj < 16; jj++) m_new = fmaxf(m_new, s[jj]);
            const float corr = exp2f((m_run - m_new) * LOG2E);
            float psum = 0.f;
#pragma unroll
            for (int jj = 0; jj < 16; jj++) {
                float p = exp2f((s[jj] - m_new) * LOG2E);
                s[jj] = p;
                psum += p;
            }
            l_run = l_run * corr + psum;
            m_run = m_new;
#pragma unroll
            for (int d = 0; d < 64; d++) o[d] *= corr;
#pragma unroll
            for (int jj = 0; jj < 16; jj++) {
                const float p = s[jj];
                const int j = c * 16 + jj;
#pragma unroll
                for (int d4 = 0; d4 < 16; d4++) {
                    float4 v = *(const float4*)&Vs[j][d4 * 4];
                    o[d4 * 4 + 0] += p * v.x;
                    o[d4 * 4 + 1] += p * v.y;
                    o[d4 * 4 + 2] += p * v.z;
                    o[d4 * 4 + 3] += p * v.w;
                }
            }
        }
        __syncthreads();
    }

    const float inv_l = 1.0f / l_run;
    float* optr = O + (size_t)gi * DMODEL + h * HD;
#pragma unroll
    for (int d4 = 0; d4 < 16; d4++) {
        float4 out;
        out.x = o[d4 * 4 + 0] * inv_l;
        out.y = o[d4 * 4 + 1] * inv_l;
        out.z = o[d4 * 4 + 2] * inv_l;
        out.w = o[d4 * 4 + 3] * inv_l;
        *(float4*)(optr + d4 * 4) = out;
    }
}

// ---------------------------------------------------------------------------
extern "C" void kernel_launch(void* const* d_in, const int* in_sizes, int n_in,
                              void* d_out, int out_size)
{
    const float* x   = (const float*)d_in[0];   // [1,4096,1024]
    const float* W_q = (const float*)d_in[1];   // [1024,1024]
    const float* W_k = (const float*)d_in[2];
    const float* W_v = (const float*)d_in[3];
    const float* W_o = (const float*)d_in[4];
    const float* b_o = (const float*)d_in[5];   // [1024]
    float* out = (float*)d_out;

    float *qp, *kp, *vp, *cp;
    cudaGetSymbolAddress((void**)&qp, g_Q);
    cudaGetSymbolAddress((void**)&kp, g_K);
    cudaGetSymbolAddress((void**)&vp, g_V);
    cudaGetSymbolAddress((void**)&cp, g_C);

    dim3 gemm_grid(DMODEL / 64, N_TOK / 64);   // (16, 64)
    sgemm64<false><<<gemm_grid, 256>>>(x, W_q, nullptr, qp, N_TOK, DMODEL, DMODEL);
    sgemm64<false><<<gemm_grid, 256>>>(x, W_k, nullptr, kp, N_TOK, DMODEL, DMODEL);
    sgemm64<false><<<gemm_grid, 256>>>(x, W_v, nullptr, vp, N_TOK, DMODEL, DMODEL);

    dim3 attn_grid(N_TOK / 64, NHEAD);         // (64, 16)
    flash_attn<<<attn_grid, 64>>>(qp, kp, vp, cp);

    sgemm64<true><<<gemm_grid, 256>>>(cp, W_o, b_o, out, N_TOK, DMODEL, DMODEL);
}

// round 6
// speedup vs baseline: 1.1802x; 1.1802x over previous
#include <cuda_runtime.h>
#include <cuda_bf16.h>
#include <cstdint>

#define N_TOK 4096
#define DMODEL 1024
#define NHEAD  16
#define HD     64
#define GK     1024

// ---------------- scratch (__device__ globals; no allocation allowed) -------
__device__ float g_Q[N_TOK * DMODEL];
__device__ float g_K[N_TOK * DMODEL];
__device__ float g_V[N_TOK * DMODEL];
__device__ float g_C[N_TOK * DMODEL];

__device__ __nv_bfloat16 g_xhi[N_TOK * DMODEL];
__device__ __nv_bfloat16 g_xlo[N_TOK * DMODEL];
__device__ __nv_bfloat16 g_chi[N_TOK * DMODEL];
__device__ __nv_bfloat16 g_clo[N_TOK * DMODEL];

__device__ __nv_bfloat16 g_wq_hi[DMODEL * DMODEL];
__device__ __nv_bfloat16 g_wq_lo[DMODEL * DMODEL];
__device__ __nv_bfloat16 g_wk_hi[DMODEL * DMODEL];
__device__ __nv_bfloat16 g_wk_lo[DMODEL * DMODEL];
__device__ __nv_bfloat16 g_wv_hi[DMODEL * DMODEL];
__device__ __nv_bfloat16 g_wv_lo[DMODEL * DMODEL];
__device__ __nv_bfloat16 g_wo_hi[DMODEL * DMODEL];
__device__ __nv_bfloat16 g_wo_lo[DMODEL * DMODEL];

// ---------------- split conversions ------------------------------------------
__global__ void __launch_bounds__(256) split_bf16(const float* __restrict__ src,
                                                  __nv_bfloat16* __restrict__ hi,
                                                  __nv_bfloat16* __restrict__ lo)
{
    int idx = blockIdx.x * 256 + threadIdx.x;
    int i4 = idx * 4;
    float4 v = *(const float4*)(src + i4);
    __nv_bfloat16 h0 = __float2bfloat16(v.x);
    __nv_bfloat16 h1 = __float2bfloat16(v.y);
    __nv_bfloat16 h2 = __float2bfloat16(v.z);
    __nv_bfloat16 h3 = __float2bfloat16(v.w);
    __nv_bfloat16 l0 = __float2bfloat16(v.x - __bfloat162float(h0));
    __nv_bfloat16 l1 = __float2bfloat16(v.y - __bfloat162float(h1));
    __nv_bfloat16 l2 = __float2bfloat16(v.z - __bfloat162float(h2));
    __nv_bfloat16 l3 = __float2bfloat16(v.w - __bfloat162float(h3));
    __nv_bfloat162 hp0; hp0.x = h0; hp0.y = h1;
    __nv_bfloat162 hp1; hp1.x = h2; hp1.y = h3;
    __nv_bfloat162 lp0; lp0.x = l0; lp0.y = l1;
    __nv_bfloat162 lp1; lp1.x = l2; lp1.y = l3;
    uint2 hv; hv.x = *(uint32_t*)&hp0; hv.y = *(uint32_t*)&hp1;
    uint2 lv; lv.x = *(uint32_t*)&lp0; lv.y = *(uint32_t*)&lp1;
    *(uint2*)(hi + i4) = hv;
    *(uint2*)(lo + i4) = lv;
}

// W [K=1024, N=1024] fp32 -> Wt hi/lo [N, K] bf16 (transposed split)
__global__ void __launch_bounds__(256) splitT_bf16(const float* __restrict__ W,
                                                   __nv_bfloat16* __restrict__ Thi,
                                                   __nv_bfloat16* __restrict__ Tlo)
{
    __shared__ float t[32][33];
    const int bk = blockIdx.x * 32;
    const int bn = blockIdx.y * 32;
    const int x = threadIdx.x;
    const int y = threadIdx.y;
#pragma unroll
    for (int r = 0; r < 32; r += 8)
        t[y + r][x] = W[(size_t)(bk + y + r) * DMODEL + bn + x];
    __syncthreads();
#pragma unroll
    for (int r = 0; r < 32; r += 8) {
        float v = t[x][y + r];
        __nv_bfloat16 h = __float2bfloat16(v);
        __nv_bfloat16 l = __float2bfloat16(v - __bfloat162float(h));
        size_t o = (size_t)(bn + y + r) * GK + bk + x;
        Thi[o] = h;
        Tlo[o] = l;
    }
}

// ---------------- mma.sync bf16 GEMM -----------------------------------------
// C[M,N] = A[M,K] * B[N,K]^T (+bias). Tile 128x128, BK=32, 256 threads.
// 2-term bf16 split: acc += Ahi*Bhi + Ahi*Blo + Alo*Bhi (fp32 accumulate).
__device__ __forceinline__ void mma16816(float* d, const uint32_t* a, const uint32_t* b)
{
    asm volatile(
        "mma.sync.aligned.m16n8k16.row.col.f32.bf16.bf16.f32 "
        "{%0,%1,%2,%3}, {%4,%5,%6,%7}, {%8,%9}, {%0,%1,%2,%3};\n"
        : "+f"(d[0]), "+f"(d[1]), "+f"(d[2]), "+f"(d[3])
        : "r"(a[0]), "r"(a[1]), "r"(a[2]), "r"(a[3]), "r"(b[0]), "r"(b[1]));
}

#define RSTRIDE 80                       // 64B data + 16B pad -> conflict-free LDS
#define TILE_SM (128 * RSTRIDE)          // 10240 B per tile

__global__ void __launch_bounds__(256, 1) gemm_mma(
    const __nv_bfloat16* __restrict__ Ahi, const __nv_bfloat16* __restrict__ Alo,
    const __nv_bfloat16* __restrict__ Bhi, const __nv_bfloat16* __restrict__ Blo,
    const float* __restrict__ bias,
    float* __restrict__ C)
{
    __shared__ char smem[4 * TILE_SM];   // Ahi | Alo | Bhi | Blo
    char* sAhi = smem;
    char* sAlo = smem + TILE_SM;
    char* sBhi = smem + 2 * TILE_SM;
    char* sBlo = smem + 3 * TILE_SM;

    const int t = threadIdx.x;
    const int lane = t & 31;
    const int wid = t >> 5;
    const int warp_m = wid & 1;          // 2 warps in M -> 64 rows each
    const int warp_n = wid >> 1;         // 4 warps in N -> 32 cols each
    const int bm = blockIdx.y * 128;
    const int bn = blockIdx.x * 128;

    const int qr = lane >> 2;            // 0..7
    const int qk4 = (lane & 3) * 4;      // byte offset of k-pair

    float acc[4][4][4];
#pragma unroll
    for (int i = 0; i < 4; i++)
#pragma unroll
        for (int j = 0; j < 4; j++)
#pragma unroll
            for (int v = 0; v < 4; v++) acc[i][j][v] = 0.0f;

    // global->smem load mapping: f = i*256 + t; row = f/4; 16B chunk c = f%4
    const int lrow = t >> 2;
    const int lc = t & 3;

    for (int kc = 0; kc < GK; kc += 32) {
        __syncthreads();                 // previous chunk's reads done
#pragma unroll
        for (int i = 0; i < 2; i++) {
            const int row = lrow + i * 64;
            const uint32_t so = (uint32_t)row * RSTRIDE + (uint32_t)lc * 16;
            const size_t ga = (size_t)(bm + row) * GK + kc + lc * 8;
            const size_t gb = (size_t)(bn + row) * GK + kc + lc * 8;
            *(uint4*)(sAhi + so) = *(const uint4*)(Ahi + ga);
            *(uint4*)(sAlo + so) = *(const uint4*)(Alo + ga);
            *(uint4*)(sBhi + so) = *(const uint4*)(Bhi + gb);
            *(uint4*)(sBlo + so) = *(const uint4*)(Blo + gb);
        }
        __syncthreads();

#pragma unroll
        for (int k16 = 0; k16 < 2; k16++) {
            const int kb = k16 * 32;     // byte offset of k16-step within row

            // B fragments: 4 n-atoms x {hi,lo} x 2 regs
            uint32_t bh[4][2], bl[4][2];
#pragma unroll
            for (int na = 0; na < 4; na++) {
                const uint32_t nb = (uint32_t)(warp_n * 32 + na * 8 + qr) * RSTRIDE + kb + qk4;
                bh[na][0] = *(const uint32_t*)(sBhi + nb);
                bh[na][1] = *(const uint32_t*)(sBhi + nb + 16);
                bl[na][0] = *(const uint32_t*)(sBlo + nb);
                bl[na][1] = *(const uint32_t*)(sBlo + nb + 16);
            }

#pragma unroll
            for (int ma = 0; ma < 4; ma++) {
                const uint32_t ab = (uint32_t)(warp_m * 64 + ma * 16 + qr) * RSTRIDE + kb + qk4;
                uint32_t ah[4], al[4];
                ah[0] = *(const uint32_t*)(sAhi + ab);
                ah[1] = *(const uint32_t*)(sAhi + ab + 8 * RSTRIDE);
                ah[2] = *(const uint32_t*)(sAhi + ab + 16);
                ah[3] = *(const uint32_t*)(sAhi + ab + 8 * RSTRIDE + 16);
                al[0] = *(const uint32_t*)(sAlo + ab);
                al[1] = *(const uint32_t*)(sAlo + ab + 8 * RSTRIDE);
                al[2] = *(const uint32_t*)(sAlo + ab + 16);
                al[3] = *(const uint32_t*)(sAlo + ab + 8 * RSTRIDE + 16);

#pragma unroll
                for (int na = 0; na < 4; na++) mma16816(acc[ma][na], ah, bh[na]);
#pragma unroll
                for (int na = 0; na < 4; na++) mma16816(acc[ma][na], ah, bl[na]);
#pragma unroll
                for (int na = 0; na < 4; na++) mma16816(acc[ma][na], al, bh[na]);
            }
        }
    }

    // epilogue
#pragma unroll
    for (int ma = 0; ma < 4; ma++) {
        const int row0 = bm + warp_m * 64 + ma * 16 + qr;
#pragma unroll
        for (int na = 0; na < 4; na++) {
            const int col = bn + warp_n * 32 + na * 8 + (lane & 3) * 2;
            float b0 = 0.f, b1 = 0.f;
            if (bias) { b0 = bias[col]; b1 = bias[col + 1]; }
            float2 o0, o1;
            o0.x = acc[ma][na][0] + b0;
            o0.y = acc[ma][na][1] + b1;
            o1.x = acc[ma][na][2] + b0;
            o1.y = acc[ma][na][3] + b1;
            *(float2*)(C + (size_t)row0 * DMODEL + col) = o0;
            *(float2*)(C + (size_t)(row0 + 8) * DMODEL + col) = o1;
        }
    }
}

// ---------------------------------------------------------------------------
// Causal flash attention, fp32 (unchanged; passing since R3).
// ---------------------------------------------------------------------------
__global__ void __launch_bounds__(64) flash_attn(const float* __restrict__ Q,
                                                 const float* __restrict__ K,
                                                 const float* __restrict__ V,
                                                 float* __restrict__ O)
{
    __shared__ float Ks[64][64];
    __shared__ float Vs[64][64];

    const int t  = threadIdx.x;
    const int qb = blockIdx.x;
    const int h  = blockIdx.y;
    const int gi = qb * 64 + t;
    const float LOG2E = 1.4426950408889634f;
    const float scale = 0.125f;

    float q[64];
    {
        const float* qptr = Q + (size_t)gi * DMODEL + h * HD;
#pragma unroll
        for (int d4 = 0; d4 < 16; d4++) {
            float4 v = *(const float4*)(qptr + d4 * 4);
            q[d4 * 4 + 0] = v.x * scale;
            q[d4 * 4 + 1] = v.y * scale;
            q[d4 * 4 + 2] = v.z * scale;
            q[d4 * 4 + 3] = v.w * scale;
        }
    }

    float o[64];
#pragma unroll
    for (int d = 0; d < 64; d++) o[d] = 0.0f;
    float m_run = -1e30f;
    float l_run = 0.0f;

    const int nkb = qb + 1;
    for (int kb = 0; kb < nkb; kb++) {
        const int j0 = kb * 64;
        const float* kbase = K + (size_t)j0 * DMODEL + h * HD;
        const float* vbase = V + (size_t)j0 * DMODEL + h * HD;
#pragma unroll
        for (int r = 0; r < 16; r++) {
            int f   = r * 64 + t;
            int row = f >> 4;
            int c4  = (f & 15) * 4;
            *(float4*)&Ks[row][c4] = *(const float4*)(kbase + (size_t)row * DMODEL + c4);
            *(float4*)&Vs[row][c4] = *(const float4*)(vbase + (size_t)row * DMODEL + c4);
        }
        __syncthreads();

        const bool diag = (kb == qb);

#pragma unroll 1
        for (int c = 0; c < 4; c++) {
            float s[16];
#pragma unroll
            for (int jj = 0; jj < 16; jj++) {
                const int j = c * 16 + jj;
                float acc0 = 0.f, acc1 = 0.f;
#pragma unroll
                for (int d4 = 0; d4 < 16; d4++) {
                    float4 kv = *(const float4*)&Ks[j][d4 * 4];
                    acc0 += q[d4 * 4 + 0] * kv.x;
                    acc1 += q[d4 * 4 + 1] * kv.y;
                    acc0 += q[d4 * 4 + 2] * kv.z;
                    acc1 += q[d4 * 4 + 3] * kv.w;
                }
                s[jj] = acc0 + acc1;
            }
            if (diag) {
#pragma unroll
                for (int jj = 0; jj < 16; jj++)
                    if (j0 + c * 16 + jj > gi) s[jj] = -1e30f;
            }
            float m_new = m_run;
#pragma unroll
            for (int jj = 0; jj < 16; jj++) m_new = fmaxf(m_new, s[jj]);
            const float corr = exp2f((m_run - m_new) * LOG2E);
            float psum = 0.f;
#pragma unroll
            for (int jj = 0; jj < 16; jj++) {
                float p = exp2f((s[jj] - m_new) * LOG2E);
                s[jj] = p;
                psum += p;
            }
            l_run = l_run * corr + psum;
            m_run = m_new;
#pragma unroll
            for (int d = 0; d < 64; d++) o[d] *= corr;
#pragma unroll
            for (int jj = 0; jj < 16; jj++) {
                const float p = s[jj];
                const int j = c * 16 + jj;
#pragma unroll
                for (int d4 = 0; d4 < 16; d4++) {
                    float4 v = *(const float4*)&Vs[j][d4 * 4];
                    o[d4 * 4 + 0] += p * v.x;
                    o[d4 * 4 + 1] += p * v.y;
                    o[d4 * 4 + 2] += p * v.z;
                    o[d4 * 4 + 3] += p * v.w;
                }
            }
        }
        __syncthreads();
    }

    const float inv_l = 1.0f / l_run;
    float* optr = O + (size_t)gi * DMODEL + h * HD;
#pragma unroll
    for (int d4 = 0; d4 < 16; d4++) {
        float4 out;
        out.x = o[d4 * 4 + 0] * inv_l;
        out.y = o[d4 * 4 + 1] * inv_l;
        out.z = o[d4 * 4 + 2] * inv_l;
        out.w = o[d4 * 4 + 3] * inv_l;
        *(float4*)(optr + d4 * 4) = out;
    }
}

// ---------------------------------------------------------------------------
extern "C" void kernel_launch(void* const* d_in, const int* in_sizes, int n_in,
                              void* d_out, int out_size)
{
    const float* x   = (const float*)d_in[0];
    const float* W_q = (const float*)d_in[1];
    const float* W_k = (const float*)d_in[2];
    const float* W_v = (const float*)d_in[3];
    const float* W_o = (const float*)d_in[4];
    const float* b_o = (const float*)d_in[5];
    float* out = (float*)d_out;

    float *qp, *kp, *vp, *cp;
    cudaGetSymbolAddress((void**)&qp, g_Q);
    cudaGetSymbolAddress((void**)&kp, g_K);
    cudaGetSymbolAddress((void**)&vp, g_V);
    cudaGetSymbolAddress((void**)&cp, g_C);

    __nv_bfloat16 *xhi, *xlo, *chi, *clo;
    __nv_bfloat16 *wqh, *wql, *wkh, *wkl, *wvh, *wvl, *woh, *wol;
    cudaGetSymbolAddress((void**)&xhi, g_xhi);
    cudaGetSymbolAddress((void**)&xlo, g_xlo);
    cudaGetSymbolAddress((void**)&chi, g_chi);
    cudaGetSymbolAddress((void**)&clo, g_clo);
    cudaGetSymbolAddress((void**)&wqh, g_wq_hi);
    cudaGetSymbolAddress((void**)&wql, g_wq_lo);
    cudaGetSymbolAddress((void**)&wkh, g_wk_hi);
    cudaGetSymbolAddress((void**)&wkl, g_wk_lo);
    cudaGetSymbolAddress((void**)&wvh, g_wv_hi);
    cudaGetSymbolAddress((void**)&wvl, g_wv_lo);
    cudaGetSymbolAddress((void**)&woh, g_wo_hi);
    cudaGetSymbolAddress((void**)&wol, g_wo_lo);

    // split inputs to bf16 hi/lo
    split_bf16<<<(N_TOK * DMODEL) / (256 * 4), 256>>>(x, xhi, xlo);
    dim3 tgrid(DMODEL / 32, DMODEL / 32);
    dim3 tblock(32, 8);
    splitT_bf16<<<tgrid, tblock>>>(W_q, wqh, wql);
    splitT_bf16<<<tgrid, tblock>>>(W_k, wkh, wkl);
    splitT_bf16<<<tgrid, tblock>>>(W_v, wvh, wvl);
    splitT_bf16<<<tgrid, tblock>>>(W_o, woh, wol);

    // projections on tensor cores (mma.sync bf16, split accumulation)
    dim3 ggrid(DMODEL / 128, N_TOK / 128);   // (8, 32)
    gemm_mma<<<ggrid, 256>>>(xhi, xlo, wqh, wql, nullptr, qp);
    gemm_mma<<<ggrid, 256>>>(xhi, xlo, wkh, wkl, nullptr, kp);
    gemm_mma<<<ggrid, 256>>>(xhi, xlo, wvh, wvl, nullptr, vp);

    // attention (fp32 CUDA cores)
    dim3 attn_grid(N_TOK / 64, NHEAD);
    flash_attn<<<attn_grid, 64>>>(qp, kp, vp, cp);

    // output projection
    split_bf16<<<(N_TOK * DMODEL) / (256 * 4), 256>>>(cp, chi, clo);
    gemm_mma<<<ggrid, 256>>>(chi, clo, woh, wol, b_o, out);
}

// round 9
// speedup vs baseline: 2.7910x; 2.3649x over previous
#include <cuda_runtime.h>
#include <cuda_bf16.h>
#include <cstdint>

#define N_TOK 4096
#define DMODEL 1024
#define NHEAD  16
#define HD     64
#define GK     1024

// ---------------- scratch (__device__ globals; no allocation allowed) -------
__device__ float g_Q[N_TOK * DMODEL];
__device__ float g_K[N_TOK * DMODEL];
__device__ float g_V[N_TOK * DMODEL];
__device__ float g_C[N_TOK * DMODEL];

__device__ __nv_bfloat16 g_xhi[N_TOK * DMODEL];
__device__ __nv_bfloat16 g_xlo[N_TOK * DMODEL];
__device__ __nv_bfloat16 g_chi[N_TOK * DMODEL];
__device__ __nv_bfloat16 g_clo[N_TOK * DMODEL];

__device__ __nv_bfloat16 g_wq_hi[DMODEL * DMODEL];
__device__ __nv_bfloat16 g_wq_lo[DMODEL * DMODEL];
__device__ __nv_bfloat16 g_wk_hi[DMODEL * DMODEL];
__device__ __nv_bfloat16 g_wk_lo[DMODEL * DMODEL];
__device__ __nv_bfloat16 g_wv_hi[DMODEL * DMODEL];
__device__ __nv_bfloat16 g_wv_lo[DMODEL * DMODEL];
__device__ __nv_bfloat16 g_wo_hi[DMODEL * DMODEL];
__device__ __nv_bfloat16 g_wo_lo[DMODEL * DMODEL];

// attention operands, head-major bf16
__device__ __nv_bfloat16 g_qh[NHEAD * N_TOK * HD];
__device__ __nv_bfloat16 g_ql[NHEAD * N_TOK * HD];
__device__ __nv_bfloat16 g_kh[NHEAD * N_TOK * HD];
__device__ __nv_bfloat16 g_kl[NHEAD * N_TOK * HD];
__device__ __nv_bfloat16 g_vth[NHEAD * HD * N_TOK];   // V^T: [h][dim][token]
__device__ __nv_bfloat16 g_vtl[NHEAD * HD * N_TOK];

// ---------------- helpers ----------------------------------------------------
__device__ __forceinline__ void mma16816(float* d, const uint32_t* a, const uint32_t* b)
{
    asm volatile(
        "mma.sync.aligned.m16n8k16.row.col.f32.bf16.bf16.f32 "
        "{%0,%1,%2,%3}, {%4,%5,%6,%7}, {%8,%9}, {%0,%1,%2,%3};\n"
        : "+f"(d[0]), "+f"(d[1]), "+f"(d[2]), "+f"(d[3])
        : "r"(a[0]), "r"(a[1]), "r"(a[2]), "r"(a[3]), "r"(b[0]), "r"(b[1]));
}
__device__ __forceinline__ uint32_t pack_bf16x2(float lo, float hi)
{
    uint32_t d;
    asm("cvt.rn.bf16x2.f32 %0, %1, %2;" : "=r"(d) : "f"(hi), "f"(lo));
    return d;
}
__device__ __forceinline__ float bf16_round(float v)
{
    return __bfloat162float(__float2bfloat16(v));
}
__device__ __forceinline__ float fast_exp2(float x)
{
    float r;
    asm("ex2.approx.ftz.f32 %0, %1;" : "=f"(r) : "f"(x));
    return r;
}

// ---------------- split conversions ------------------------------------------
__global__ void __launch_bounds__(256) split_bf16(const float* __restrict__ src,
                                                  __nv_bfloat16* __restrict__ hi,
                                                  __nv_bfloat16* __restrict__ lo)
{
    int idx = blockIdx.x * 256 + threadIdx.x;
    int i4 = idx * 4;
    float4 v = *(const float4*)(src + i4);
    float h0 = bf16_round(v.x), h1 = bf16_round(v.y);
    float h2 = bf16_round(v.z), h3 = bf16_round(v.w);
    uint2 hv, lv;
    hv.x = pack_bf16x2(h0, h1);
    hv.y = pack_bf16x2(h2, h3);
    lv.x = pack_bf16x2(v.x - h0, v.y - h1);
    lv.y = pack_bf16x2(v.z - h2, v.w - h3);
    *(uint2*)(hi + i4) = hv;
    *(uint2*)(lo + i4) = lv;
}

// W [K,N] fp32 -> Wt hi/lo [N,K] bf16 (transposed split)
__global__ void __launch_bounds__(256) splitT_bf16(const float* __restrict__ W,
                                                   __nv_bfloat16* __restrict__ Thi,
                                                   __nv_bfloat16* __restrict__ Tlo)
{
    __shared__ float t[32][33];
    const int bk = blockIdx.x * 32;
    const int bn = blockIdx.y * 32;
    const int x = threadIdx.x;
    const int y = threadIdx.y;
#pragma unroll
    for (int r = 0; r < 32; r += 8)
        t[y + r][x] = W[(size_t)(bk + y + r) * DMODEL + bn + x];
    __syncthreads();
#pragma unroll
    for (int r = 0; r < 32; r += 8) {
        float v = t[x][y + r];
        float h = bf16_round(v);
        size_t o = (size_t)(bn + y + r) * GK + bk + x;
        Thi[o] = __float2bfloat16(h);
        Tlo[o] = __float2bfloat16(v - h);
    }
}

// [tok][h*64+d] fp32 -> head-major bf16 hi/lo [h][tok][64], scaled
__global__ void __launch_bounds__(256) split_head(const float* __restrict__ src,
                                                  __nv_bfloat16* __restrict__ hi,
                                                  __nv_bfloat16* __restrict__ lo,
                                                  float scale)
{
    int idx = blockIdx.x * 256 + threadIdx.x;
    int i4 = idx * 4;
    int tok = i4 >> 10;
    int c = i4 & 1023;
    int h = c >> 6;
    int d = c & 63;
    float4 v = *(const float4*)(src + i4);
    v.x *= scale; v.y *= scale; v.z *= scale; v.w *= scale;
    float h0 = bf16_round(v.x), h1 = bf16_round(v.y);
    float h2 = bf16_round(v.z), h3 = bf16_round(v.w);
    size_t off = ((size_t)h * N_TOK + tok) * HD + d;
    uint2 hv, lv;
    hv.x = pack_bf16x2(h0, h1);
    hv.y = pack_bf16x2(h2, h3);
    lv.x = pack_bf16x2(v.x - h0, v.y - h1);
    lv.y = pack_bf16x2(v.z - h2, v.w - h3);
    *(uint2*)(hi + off) = hv;
    *(uint2*)(lo + off) = lv;
}

// V [tok][h*64+d] fp32 -> V^T bf16 hi/lo [h][d][tok]
__global__ void __launch_bounds__(256) split_vT(const float* __restrict__ V,
                                                __nv_bfloat16* __restrict__ th,
                                                __nv_bfloat16* __restrict__ tl)
{
    __shared__ float s[64][68];   // 68 floats = 272B row stride: float4-aligned rows
    const int h = blockIdx.y;
    const int tok0 = blockIdx.x * 64;
    const int t = threadIdx.x;
#pragma unroll
    for (int i = 0; i < 4; i++) {
        int f = i * 256 + t;
        int r = f >> 4;
        int c4 = (f & 15) * 4;
        *(float4*)&s[r][c4] = *(const float4*)(V + (size_t)(tok0 + r) * DMODEL + h * HD + c4);
    }
    __syncthreads();
#pragma unroll
    for (int i = 0; i < 4; i++) {
        int f = i * 256 + t;
        int d = f >> 4;
        int tk4 = (f & 15) * 4;
        float v0 = s[tk4 + 0][d], v1 = s[tk4 + 1][d];
        float v2 = s[tk4 + 2][d], v3 = s[tk4 + 3][d];
        float h0 = bf16_round(v0), h1 = bf16_round(v1);
        float h2 = bf16_round(v2), h3 = bf16_round(v3);
        size_t off = ((size_t)(h * HD + d)) * N_TOK + tok0 + tk4;
        uint2 hv, lv;
        hv.x = pack_bf16x2(h0, h1);
        hv.y = pack_bf16x2(h2, h3);
        lv.x = pack_bf16x2(v0 - h0, v1 - h1);
        lv.y = pack_bf16x2(v2 - h2, v3 - h3);
        *(uint2*)(th + off) = hv;
        *(uint2*)(tl + off) = lv;
    }
}

// ---------------- mma.sync bf16 GEMM (unchanged, passing) --------------------
#define RSTRIDE 80
#define TILE_SM (128 * RSTRIDE)

__global__ void __launch_bounds__(256, 1) gemm_mma(
    const __nv_bfloat16* __restrict__ Ahi, const __nv_bfloat16* __restrict__ Alo,
    const __nv_bfloat16* __restrict__ Bhi, const __nv_bfloat16* __restrict__ Blo,
    const float* __restrict__ bias,
    float* __restrict__ C)
{
    __shared__ char smem[4 * TILE_SM];
    char* sAhi = smem;
    char* sAlo = smem + TILE_SM;
    char* sBhi = smem + 2 * TILE_SM;
    char* sBlo = smem + 3 * TILE_SM;

    const int t = threadIdx.x;
    const int lane = t & 31;
    const int wid = t >> 5;
    const int warp_m = wid & 1;
    const int warp_n = wid >> 1;
    const int bm = blockIdx.y * 128;
    const int bn = blockIdx.x * 128;

    const int qr = lane >> 2;
    const int qk4 = (lane & 3) * 4;

    float acc[4][4][4];
#pragma unroll
    for (int i = 0; i < 4; i++)
#pragma unroll
        for (int j = 0; j < 4; j++)
#pragma unroll
            for (int v = 0; v < 4; v++) acc[i][j][v] = 0.0f;

    const int lrow = t >> 2;
    const int lc = t & 3;

    for (int kc = 0; kc < GK; kc += 32) {
        __syncthreads();
#pragma unroll
        for (int i = 0; i < 2; i++) {
            const int row = lrow + i * 64;
            const uint32_t so = (uint32_t)row * RSTRIDE + (uint32_t)lc * 16;
            const size_t ga = (size_t)(bm + row) * GK + kc + lc * 8;
            const size_t gb = (size_t)(bn + row) * GK + kc + lc * 8;
            *(uint4*)(sAhi + so) = *(const uint4*)(Ahi + ga);
            *(uint4*)(sAlo + so) = *(const uint4*)(Alo + ga);
            *(uint4*)(sBhi + so) = *(const uint4*)(Bhi + gb);
            *(uint4*)(sBlo + so) = *(const uint4*)(Blo + gb);
        }
        __syncthreads();

#pragma unroll
        for (int k16 = 0; k16 < 2; k16++) {
            const int kb = k16 * 32;
            uint32_t bh[4][2], bl[4][2];
#pragma unroll
            for (int na = 0; na < 4; na++) {
                const uint32_t nb = (uint32_t)(warp_n * 32 + na * 8 + qr) * RSTRIDE + kb + qk4;
                bh[na][0] = *(const uint32_t*)(sBhi + nb);
                bh[na][1] = *(const uint32_t*)(sBhi + nb + 16);
                bl[na][0] = *(const uint32_t*)(sBlo + nb);
                bl[na][1] = *(const uint32_t*)(sBlo + nb + 16);
            }
#pragma unroll
            for (int ma = 0; ma < 4; ma++) {
                const uint32_t ab = (uint32_t)(warp_m * 64 + ma * 16 + qr) * RSTRIDE + kb + qk4;
                uint32_t ah[4], al[4];
                ah[0] = *(const uint32_t*)(sAhi + ab);
                ah[1] = *(const uint32_t*)(sAhi + ab + 8 * RSTRIDE);
                ah[2] = *(const uint32_t*)(sAhi + ab + 16);
                ah[3] = *(const uint32_t*)(sAhi + ab + 8 * RSTRIDE + 16);
                al[0] = *(const uint32_t*)(sAlo + ab);
                al[1] = *(const uint32_t*)(sAlo + ab + 8 * RSTRIDE);
                al[2] = *(const uint32_t*)(sAlo + ab + 16);
                al[3] = *(const uint32_t*)(sAlo + ab + 8 * RSTRIDE + 16);
#pragma unroll
                for (int na = 0; na < 4; na++) mma16816(acc[ma][na], ah, bh[na]);
#pragma unroll
                for (int na = 0; na < 4; na++) mma16816(acc[ma][na], ah, bl[na]);
#pragma unroll
                for (int na = 0; na < 4; na++) mma16816(acc[ma][na], al, bh[na]);
            }
        }
    }

#pragma unroll
    for (int ma = 0; ma < 4; ma++) {
        const int row0 = bm + warp_m * 64 + ma * 16 + qr;
#pragma unroll
        for (int na = 0; na < 4; na++) {
            const int col = bn + warp_n * 32 + na * 8 + (lane & 3) * 2;
            float b0 = 0.f, b1 = 0.f;
            if (bias) { b0 = bias[col]; b1 = bias[col + 1]; }
            float2 o0, o1;
            o0.x = acc[ma][na][0] + b0;
            o0.y = acc[ma][na][1] + b1;
            o1.x = acc[ma][na][2] + b0;
            o1.y = acc[ma][na][3] + b1;
            *(float2*)(C + (size_t)row0 * DMODEL + col) = o0;
            *(float2*)(C + (size_t)(row0 + 8) * DMODEL + col) = o1;
        }
    }
}

// ---------------- tensor-core causal flash attention -------------------------
// CTA = (128 query rows, 1 head), 256 threads, warp w owns rows w*16..w*16+15.
// Hi/lo split on Q,K,P,V (3 mma passes each). Q pre-scaled by 0.125*log2(e).
#define ASTRIDE 144   // 128B data + 16B pad: conflict-free fragment LDS, 16B-aligned rows

__global__ void __launch_bounds__(256) flash_mma(
    const __nv_bfloat16* __restrict__ qh, const __nv_bfloat16* __restrict__ ql,
    const __nv_bfloat16* __restrict__ kh, const __nv_bfloat16* __restrict__ kl,
    const __nv_bfloat16* __restrict__ vth, const __nv_bfloat16* __restrict__ vtl,
    float* __restrict__ C)
{
    __shared__ __align__(16) char sKh[64 * ASTRIDE];
    __shared__ __align__(16) char sKl[64 * ASTRIDE];
    __shared__ __align__(16) char sVh[64 * ASTRIDE];
    __shared__ __align__(16) char sVl[64 * ASTRIDE];

    const int t = threadIdx.x;
    const int lane = t & 31;
    const int w = t >> 5;
    const int qb = 31 - blockIdx.x;        // heavy CTAs first
    const int h = blockIdx.y;
    const int qr = lane >> 2;
    const int qc = lane & 3;
    const int r0 = qb * 128 + w * 16 + qr; // this thread's low query row
    const int row_max = qb * 128 + w * 16 + 15;

    // Q fragments (hi/lo), loaded once
    uint32_t qfh[4][4], qfl[4][4];
    {
        const size_t base = ((size_t)h * N_TOK + r0) * HD;
#pragma unroll
        for (int ks = 0; ks < 4; ks++) {
            const int d0 = ks * 16 + 2 * qc;
            qfh[ks][0] = *(const uint32_t*)(qh + base + d0);
            qfh[ks][1] = *(const uint32_t*)(qh + base + 8 * HD + d0);
            qfh[ks][2] = *(const uint32_t*)(qh + base + d0 + 8);
            qfh[ks][3] = *(const uint32_t*)(qh + base + 8 * HD + d0 + 8);
            qfl[ks][0] = *(const uint32_t*)(ql + base + d0);
            qfl[ks][1] = *(const uint32_t*)(ql + base + 8 * HD + d0);
            qfl[ks][2] = *(const uint32_t*)(ql + base + d0 + 8);
            qfl[ks][3] = *(const uint32_t*)(ql + base + 8 * HD + d0 + 8);
        }
    }

    float o_[8][4];
#pragma unroll
    for (int na = 0; na < 8; na++)
#pragma unroll
        for (int j = 0; j < 4; j++) o_[na][j] = 0.0f;
    float m_[2] = {-1e30f, -1e30f};
    float l_[2] = {0.0f, 0.0f};

    const int kb_max = 2 * qb + 1;
    for (int kb = 0; kb <= kb_max; kb++) {
        __syncthreads();   // previous block's fragment reads done
        // load K/V^T tiles (hi+lo), 8KB each, coalesced
        {
            const size_t kgo = ((size_t)h * N_TOK + kb * 64) * HD;
#pragma unroll
            for (int i = 0; i < 2; i++) {
                const int f = i * 256 + t;          // 0..511
                const int row = f >> 3;
                const int c = f & 7;
                const uint32_t so = (uint32_t)row * ASTRIDE + (uint32_t)c * 16;
                *(uint4*)(sKh + so) = *(const uint4*)(kh + kgo + (size_t)row * HD + c * 8);
                *(uint4*)(sKl + so) = *(const uint4*)(kl + kgo + (size_t)row * HD + c * 8);
                const size_t vgo = ((size_t)(h * HD + row)) * N_TOK + kb * 64 + c * 8;
                *(uint4*)(sVh + so) = *(const uint4*)(vth + vgo);
                *(uint4*)(sVl + so) = *(const uint4*)(vtl + vgo);
            }
        }
        __syncthreads();

        if (kb * 64 <= row_max) {
            // --- S = Q K^T (3 passes) ---
            float s_[8][4];
#pragma unroll
            for (int na = 0; na < 8; na++)
#pragma unroll
                for (int j = 0; j < 4; j++) s_[na][j] = 0.0f;

#pragma unroll
            for (int ks = 0; ks < 4; ks++) {
                uint32_t bh[8][2], bl[8][2];
#pragma unroll
                for (int na = 0; na < 8; na++) {
                    const uint32_t a = (uint32_t)(na * 8 + qr) * ASTRIDE + ks * 32 + qc * 4;
                    bh[na][0] = *(const uint32_t*)(sKh + a);
                    bh[na][1] = *(const uint32_t*)(sKh + a + 16);
                    bl[na][0] = *(const uint32_t*)(sKl + a);
                    bl[na][1] = *(const uint32_t*)(sKl + a + 16);
                }
#pragma unroll
                for (int na = 0; na < 8; na++) mma16816(s_[na], qfh[ks], bh[na]);
#pragma unroll
                for (int na = 0; na < 8; na++) mma16816(s_[na], qfl[ks], bh[na]);
#pragma unroll
                for (int na = 0; na < 8; na++) mma16816(s_[na], qfh[ks], bl[na]);
            }

            // --- causal mask (diagonal blocks only) ---
            if (kb >= 2 * qb) {
#pragma unroll
                for (int na = 0; na < 8; na++) {
                    const int key0 = kb * 64 + na * 8 + 2 * qc;
                    if (key0 > r0)     s_[na][0] = -1e30f;
                    if (key0 + 1 > r0) s_[na][1] = -1e30f;
                    if (key0 > r0 + 8)     s_[na][2] = -1e30f;
                    if (key0 + 1 > r0 + 8) s_[na][3] = -1e30f;
                }
            }

            // --- online softmax (scores already in log2 domain) ---
            float corr[2];
#pragma unroll
            for (int r = 0; r < 2; r++) {
                float mx = -1e30f;
#pragma unroll
                for (int na = 0; na < 8; na++) {
                    mx = fmaxf(mx, s_[na][2 * r]);
                    mx = fmaxf(mx, s_[na][2 * r + 1]);
                }
                mx = fmaxf(mx, __shfl_xor_sync(0xffffffffu, mx, 1));
                mx = fmaxf(mx, __shfl_xor_sync(0xffffffffu, mx, 2));
                const float m_new = fmaxf(m_[r], mx);
                corr[r] = fast_exp2(m_[r] - m_new);
                m_[r] = m_new;
                float psum = 0.0f;
#pragma unroll
                for (int na = 0; na < 8; na++) {
                    float p0 = fast_exp2(s_[na][2 * r] - m_new);
                    float p1 = fast_exp2(s_[na][2 * r + 1] - m_new);
                    s_[na][2 * r] = p0;
                    s_[na][2 * r + 1] = p1;
                    psum += p0 + p1;
                }
                l_[r] = l_[r] * corr[r] + psum;
            }
#pragma unroll
            for (int na = 0; na < 8; na++) {
                o_[na][0] *= corr[0];
                o_[na][1] *= corr[0];
                o_[na][2] *= corr[1];
                o_[na][3] *= corr[1];
            }

            // --- P fragments (hi/lo), register-direct from S atoms ---
            uint32_t pah[4][4], pal[4][4];
#pragma unroll
            for (int ka = 0; ka < 4; ka++) {
                const float* pA = s_[2 * ka];
                const float* pB = s_[2 * ka + 1];
                float hA0 = bf16_round(pA[0]), hA1 = bf16_round(pA[1]);
                float hA2 = bf16_round(pA[2]), hA3 = bf16_round(pA[3]);
                float hB0 = bf16_round(pB[0]), hB1 = bf16_round(pB[1]);
                float hB2 = bf16_round(pB[2]), hB3 = bf16_round(pB[3]);
                pah[ka][0] = pack_bf16x2(hA0, hA1);
                pah[ka][1] = pack_bf16x2(hA2, hA3);
                pah[ka][2] = pack_bf16x2(hB0, hB1);
                pah[ka][3] = pack_bf16x2(hB2, hB3);
                pal[ka][0] = pack_bf16x2(pA[0] - hA0, pA[1] - hA1);
                pal[ka][1] = pack_bf16x2(pA[2] - hA2, pA[3] - hA3);
                pal[ka][2] = pack_bf16x2(pB[0] - hB0, pB[1] - hB1);
                pal[ka][3] = pack_bf16x2(pB[2] - hB2, pB[3] - hB3);
            }

            // --- O += P V (3 passes) ---
#pragma unroll
            for (int ka = 0; ka < 4; ka++) {
                uint32_t vh[8][2], vl[8][2];
#pragma unroll
                for (int na = 0; na < 8; na++) {
                    const uint32_t a = (uint32_t)(na * 8 + qr) * ASTRIDE + ka * 32 + qc * 4;
                    vh[na][0] = *(const uint32_t*)(sVh + a);
                    vh[na][1] = *(const uint32_t*)(sVh + a + 16);
                    vl[na][0] = *(const uint32_t*)(sVl + a);
                    vl[na][1] = *(const uint32_t*)(sVl + a + 16);
                }
#pragma unroll
                for (int na = 0; na < 8; na++) mma16816(o_[na], pah[ka], vh[na]);
#pragma unroll
                for (int na = 0; na < 8; na++) mma16816(o_[na], pal[ka], vh[na]);
#pragma unroll
                for (int na = 0; na < 8; na++) mma16816(o_[na], pah[ka], vl[na]);
            }
        }
    }

    // finalize: quad-reduce l, normalize, store
    float l0 = l_[0];
    l0 += __shfl_xor_sync(0xffffffffu, l0, 1);
    l0 += __shfl_xor_sync(0xffffffffu, l0, 2);
    float l1 = l_[1];
    l1 += __shfl_xor_sync(0xffffffffu, l1, 1);
    l1 += __shfl_xor_sync(0xffffffffu, l1, 2);
    const float inv0 = 1.0f / l0;
    const float inv1 = 1.0f / l1;

#pragma unroll
    for (int na = 0; na < 8; na++) {
        const int col = h * HD + na * 8 + 2 * qc;
        float2 w0, w1;
        w0.x = o_[na][0] * inv0;
        w0.y = o_[na][1] * inv0;
        w1.x = o_[na][2] * inv1;
        w1.y = o_[na][3] * inv1;
        *(float2*)(C + (size_t)r0 * DMODEL + col) = w0;
        *(float2*)(C + (size_t)(r0 + 8) * DMODEL + col) = w1;
    }
}

// ---------------------------------------------------------------------------
extern "C" void kernel_launch(void* const* d_in, const int* in_sizes, int n_in,
                              void* d_out, int out_size)
{
    const float* x   = (const float*)d_in[0];
    const float* W_q = (const float*)d_in[1];
    const float* W_k = (const float*)d_in[2];
    const float* W_v = (const float*)d_in[3];
    const float* W_o = (const float*)d_in[4];
    const float* b_o = (const float*)d_in[5];
    float* out = (float*)d_out;

    float *qp, *kp, *vp, *cp;
    cudaGetSymbolAddress((void**)&qp, g_Q);
    cudaGetSymbolAddress((void**)&kp, g_K);
    cudaGetSymbolAddress((void**)&vp, g_V);
    cudaGetSymbolAddress((void**)&cp, g_C);

    __nv_bfloat16 *xhi, *xlo, *chi, *clo;
    __nv_bfloat16 *wqh, *wql, *wkh, *wkl, *wvh, *wvl, *woh, *wol;
    __nv_bfloat16 *aqh, *aql, *akh, *akl, *avh, *avl;
    cudaGetSymbolAddress((void**)&xhi, g_xhi);
    cudaGetSymbolAddress((void**)&xlo, g_xlo);
    cudaGetSymbolAddress((void**)&chi, g_chi);
    cudaGetSymbolAddress((void**)&clo, g_clo);
    cudaGetSymbolAddress((void**)&wqh, g_wq_hi);
    cudaGetSymbolAddress((void**)&wql, g_wq_lo);
    cudaGetSymbolAddress((void**)&wkh, g_wk_hi);
    cudaGetSymbolAddress((void**)&wkl, g_wk_lo);
    cudaGetSymbolAddress((void**)&wvh, g_wv_hi);
    cudaGetSymbolAddress((void**)&wvl, g_wv_lo);
    cudaGetSymbolAddress((void**)&woh, g_wo_hi);
    cudaGetSymbolAddress((void**)&wol, g_wo_lo);
    cudaGetSymbolAddress((void**)&aqh, g_qh);
    cudaGetSymbolAddress((void**)&aql, g_ql);
    cudaGetSymbolAddress((void**)&akh, g_kh);
    cudaGetSymbolAddress((void**)&akl, g_kl);
    cudaGetSymbolAddress((void**)&avh, g_vth);
    cudaGetSymbolAddress((void**)&avl, g_vtl);

    // split x + weights
    split_bf16<<<(N_TOK * DMODEL) / (256 * 4), 256>>>(x, xhi, xlo);
    dim3 tgrid(DMODEL / 32, DMODEL / 32);
    dim3 tblock(32, 8);
    splitT_bf16<<<tgrid, tblock>>>(W_q, wqh, wql);
    splitT_bf16<<<tgrid, tblock>>>(W_k, wkh, wkl);
    splitT_bf16<<<tgrid, tblock>>>(W_v, wvh, wvl);
    splitT_bf16<<<tgrid, tblock>>>(W_o, woh, wol);

    // projections (tensor cores)
    dim3 ggrid(DMODEL / 128, N_TOK / 128);
    gemm_mma<<<ggrid, 256>>>(xhi, xlo, wqh, wql, nullptr, qp);
    gemm_mma<<<ggrid, 256>>>(xhi, xlo, wkh, wkl, nullptr, kp);
    gemm_mma<<<ggrid, 256>>>(xhi, xlo, wvh, wvl, nullptr, vp);

    // attention operand prep (scale = 1/sqrt(64) * log2(e), folded into Q)
    const float qscale = 0.125f * 1.4426950408889634f;
    split_head<<<(N_TOK * DMODEL) / (256 * 4), 256>>>(qp, aqh, aql, qscale);
    split_head<<<(N_TOK * DMODEL) / (256 * 4), 256>>>(kp, akh, akl, 1.0f);
    dim3 vgrid(N_TOK / 64, NHEAD);
    split_vT<<<vgrid, 256>>>(vp, avh, avl);

    // tensor-core causal flash attention
    dim3 agrid(N_TOK / 128, NHEAD);
    flash_mma<<<agrid, 256>>>(aqh, aql, akh, akl, avh, avl, cp);

    // output projection
    split_bf16<<<(N_TOK * DMODEL) / (256 * 4), 256>>>(cp, chi, clo);
    gemm_mma<<<ggrid, 256>>>(chi, clo, woh, wol, b_o, out);
}